// round 1
// baseline (speedup 1.0000x reference)
#include <cuda_runtime.h>
#include <math.h>

#define D_MODEL 1024
#define D_STATE 16
#define D_INNER 2048
#define BATCH   2
#define SEQ     4096
#define NTOK    (BATCH*SEQ)

// ---------------- scratch (device globals; no allocation allowed) ----------------
__device__ __align__(16) float g_PT[32 * 1024];     // [o][d] raw P^T: o<16 -> A-proj, o>=16 -> B-proj (atomic target)
__device__ __align__(16) float g_Pp[1024 * 32];     // [d][o] P' = nw[d]*P[d][o]  (for token kernel)
__device__ __align__(16) float g_MT[16 * 1024];     // [n][d] (W_out @ C)^T
__device__ float g_c[32];                           // b_in @ A (0:16), b_in @ B (16:32)
__device__ float g_k1[32];                          // sum_d nw[d]*P[d][o]
__device__ float g_k2[32];                          // sum_d nb[d]*P[d][o] + g_c[o]
__device__ __align__(16) float g_au[BATCH * 32 * SEQ];   // [b][o][s]; o<16: a (sigmoid), o>=16: u
__device__ __align__(16) float g_states[NTOK * 16];      // [b][s][n]

// ---------------- K0: zero the atomic accumulator ----------------
__global__ void k_zero() {
    int i = blockIdx.x * 256 + threadIdx.x;   // grid 128 x 256 == 32768
    g_PT[i] = 0.f;
}

// ---------------- K1: P^T[o][d] = sum_e W_in[e][d] * {A|B}[e][o]  (split-K + atomics) ----------------
// grid: (8 d-tiles) x (32 e-chunks) = 256 blocks, 128 threads
__global__ void k_pw(const float* __restrict__ Win, const float* __restrict__ A,
                     const float* __restrict__ Bs) {
    __shared__ float sA[64 * 16];
    __shared__ float sB[64 * 16];
    int tid = threadIdx.x;
    int d0 = (blockIdx.x & 7) * 128;
    int e0 = (blockIdx.x >> 3) * 64;
    for (int i = tid; i < 64 * 16; i += 128) {
        sA[i] = A[e0 * 16 + i];
        sB[i] = Bs[e0 * 16 + i];
    }
    __syncthreads();
    float acc[32];
#pragma unroll
    for (int o = 0; o < 32; o++) acc[o] = 0.f;
    int d = d0 + tid;
    for (int el = 0; el < 64; el++) {
        float w = Win[(e0 + el) * 1024 + d];
#pragma unroll
        for (int n = 0; n < 16; n++) {
            acc[n]      += w * sA[el * 16 + n];
            acc[16 + n] += w * sB[el * 16 + n];
        }
    }
#pragma unroll
    for (int o = 0; o < 32; o++) atomicAdd(&g_PT[o * 1024 + d], acc[o]);
}

// ---------------- K2: MT[n][d] = sum_e W_out[d][e]*C[e][n]; also cA/cB = b_in @ {A|B} ----------------
// grid: 1026 blocks x 256 threads (blocks 0..1023: one output row d; 1024/1025: cA/cB)
__global__ void k_m(const float* __restrict__ Wout, const float* __restrict__ C,
                    const float* __restrict__ A, const float* __restrict__ Bs,
                    const float* __restrict__ b_in) {
    int blk = blockIdx.x;
    int tid = threadIdx.x;
    int lane = tid & 31, w = tid >> 5;
    float acc[16];
#pragma unroll
    for (int n = 0; n < 16; n++) acc[n] = 0.f;

    if (blk < 1024) {
        const float* row = Wout + blk * 2048;
        for (int e = tid; e < 2048; e += 256) {
            float wv = row[e];
            const float4* c4 = (const float4*)(C + e * 16);
            float4 c0 = c4[0], c1 = c4[1], c2 = c4[2], c3 = c4[3];
            acc[0] += wv * c0.x; acc[1] += wv * c0.y; acc[2] += wv * c0.z; acc[3] += wv * c0.w;
            acc[4] += wv * c1.x; acc[5] += wv * c1.y; acc[6] += wv * c1.z; acc[7] += wv * c1.w;
            acc[8] += wv * c2.x; acc[9] += wv * c2.y; acc[10]+= wv * c2.z; acc[11]+= wv * c2.w;
            acc[12]+= wv * c3.x; acc[13]+= wv * c3.y; acc[14]+= wv * c3.z; acc[15]+= wv * c3.w;
        }
    } else {
        const float* G = (blk == 1024) ? A : Bs;
        for (int e = tid; e < 2048; e += 256) {
            float bv = b_in[e];
            const float4* g4 = (const float4*)(G + e * 16);
            float4 c0 = g4[0], c1 = g4[1], c2 = g4[2], c3 = g4[3];
            acc[0] += bv * c0.x; acc[1] += bv * c0.y; acc[2] += bv * c0.z; acc[3] += bv * c0.w;
            acc[4] += bv * c1.x; acc[5] += bv * c1.y; acc[6] += bv * c1.z; acc[7] += bv * c1.w;
            acc[8] += bv * c2.x; acc[9] += bv * c2.y; acc[10]+= bv * c2.z; acc[11]+= bv * c2.w;
            acc[12]+= bv * c3.x; acc[13]+= bv * c3.y; acc[14]+= bv * c3.z; acc[15]+= bv * c3.w;
        }
    }
#pragma unroll
    for (int off = 16; off; off >>= 1)
#pragma unroll
        for (int n = 0; n < 16; n++) acc[n] += __shfl_down_sync(0xffffffffu, acc[n], off);

    __shared__ float red[8 * 16];
    if (lane == 0) {
#pragma unroll
        for (int n = 0; n < 16; n++) red[w * 16 + n] = acc[n];
    }
    __syncthreads();
    if (tid < 16) {
        float s = 0.f;
#pragma unroll
        for (int j = 0; j < 8; j++) s += red[j * 16 + tid];
        if (blk < 1024)       g_MT[tid * 1024 + blk] = s;
        else if (blk == 1024) g_c[tid] = s;
        else                  g_c[16 + tid] = s;
    }
}

// ---------------- K3: fold LayerNorm weights into P; compute k1/k2 ----------------
// grid: 32 blocks (one per output o) x 256 threads
__global__ void k_fold(const float* __restrict__ nw, const float* __restrict__ nb) {
    int o = blockIdx.x;
    int tid = threadIdx.x;
    int lane = tid & 31, w = tid >> 5;
    float s1 = 0.f, s2 = 0.f;
    for (int d = tid; d < 1024; d += 256) {
        float p = g_PT[o * 1024 + d];
        float wn = nw[d];
        s1 += wn * p;
        s2 += nb[d] * p;
        g_Pp[d * 32 + o] = wn * p;
    }
#pragma unroll
    for (int off = 16; off; off >>= 1) {
        s1 += __shfl_down_sync(0xffffffffu, s1, off);
        s2 += __shfl_down_sync(0xffffffffu, s2, off);
    }
    __shared__ float r1[8], r2[8];
    if (lane == 0) { r1[w] = s1; r2[w] = s2; }
    __syncthreads();
    if (tid == 0) {
        float t1 = 0.f, t2 = 0.f;
#pragma unroll
        for (int j = 0; j < 8; j++) { t1 += r1[j]; t2 += r2[j]; }
        g_k1[o] = t1;
        g_k2[o] = t2 + g_c[o];
    }
}

// ---------------- K4: per-token fused LayerNorm + projections -> a (sigmoid), u ----------------
// grid: 8192 blocks (one token) x 256 threads
__global__ void k_ln(const float* __restrict__ x) {
    int t = blockIdx.x;
    int tid = threadIdx.x;
    int lane = tid & 31, w = tid >> 5;

    float dot[32];
#pragma unroll
    for (int o = 0; o < 32; o++) dot[o] = 0.f;

    float4 xv = ((const float4*)(x + t * 1024))[tid];
    const float* Pr = g_Pp + (tid * 4) * 32;
#pragma unroll
    for (int j = 0; j < 4; j++) {
        float xc = (j == 0) ? xv.x : (j == 1) ? xv.y : (j == 2) ? xv.z : xv.w;
        const float4* p4 = (const float4*)(Pr + j * 32);
#pragma unroll
        for (int q = 0; q < 8; q++) {
            float4 pv = p4[q];
            dot[q * 4 + 0] += xc * pv.x;
            dot[q * 4 + 1] += xc * pv.y;
            dot[q * 4 + 2] += xc * pv.z;
            dot[q * 4 + 3] += xc * pv.w;
        }
    }
    float s1 = xv.x + xv.y + xv.z + xv.w;
    float s2 = xv.x * xv.x + xv.y * xv.y + xv.z * xv.z + xv.w * xv.w;

    __shared__ float red[34][256];
#pragma unroll
    for (int o = 0; o < 32; o++) red[o][tid] = dot[o];
    red[32][tid] = s1;
    red[33][tid] = s2;
    __syncthreads();

    __shared__ float tot[34];
    for (int r = w; r < 34; r += 8) {
        float v = 0.f;
#pragma unroll
        for (int k = 0; k < 8; k++) v += red[r][lane + 32 * k];
#pragma unroll
        for (int off = 16; off; off >>= 1) v += __shfl_down_sync(0xffffffffu, v, off);
        if (lane == 0) tot[r] = v;
    }
    __syncthreads();

    if (tid < 32) {
        float mu   = tot[32] * (1.f / 1024.f);
        float var  = tot[33] * (1.f / 1024.f) - mu * mu;
        float rstd = rsqrtf(var + 1e-5f);
        float val  = rstd * tot[tid] - mu * rstd * g_k1[tid] + g_k2[tid];
        if (tid < 16) val = 1.f / (1.f + __expf(-val));
        int b = t >> 12, s = t & 4095;
        g_au[(b * 32 + tid) * 4096 + s] = val;
    }
}

// ---------------- K5: 32 parallel diagonal scans, s_t = a_t*s_{t-1} + u_t ----------------
// grid: 32 blocks (b,n) x 256 threads, 16 elems/thread
__global__ void k_scan() {
    int bn = blockIdx.x;
    int b = bn >> 4, n = bn & 15;
    const float* ap = g_au + (b * 32 + n) * 4096;
    const float* up = g_au + (b * 32 + 16 + n) * 4096;
    int tid = threadIdx.x;
    int lane = tid & 31, w = tid >> 5;

    float a[16], u[16];
    const float4* a4 = (const float4*)(ap + tid * 16);
    const float4* u4 = (const float4*)(up + tid * 16);
#pragma unroll
    for (int q = 0; q < 4; q++) {
        float4 av = a4[q], uv = u4[q];
        a[q*4+0] = av.x; a[q*4+1] = av.y; a[q*4+2] = av.z; a[q*4+3] = av.w;
        u[q*4+0] = uv.x; u[q*4+1] = uv.y; u[q*4+2] = uv.z; u[q*4+3] = uv.w;
    }
    // local segment composition: (Aloc, Uloc) s.t. s_out = Aloc*s_in + Uloc
    float Aloc = 1.f, Uloc = 0.f;
#pragma unroll
    for (int i = 0; i < 16; i++) { Uloc = Uloc * a[i] + u[i]; Aloc *= a[i]; }

    // warp inclusive scan of pairs (compose earlier-then-current)
    float Ai = Aloc, Ui = Uloc;
#pragma unroll
    for (int off = 1; off < 32; off <<= 1) {
        float Ap = __shfl_up_sync(0xffffffffu, Ai, off);
        float Up = __shfl_up_sync(0xffffffffu, Ui, off);
        if (lane >= off) { Ui = Up * Ai + Ui; Ai = Ap * Ai; }
    }
    __shared__ float wA[8], wU[8], pA[8], pU[8];
    if (lane == 31) { wA[w] = Ai; wU[w] = Ui; }
    __syncthreads();
    if (tid == 0) {
        float Ac = 1.f, Uc = 0.f;
#pragma unroll
        for (int j = 0; j < 8; j++) {
            pA[j] = Ac; pU[j] = Uc;
            float na = wA[j], nu = wU[j];
            Uc = Uc * na + nu;
            Ac *= na;
        }
    }
    __syncthreads();
    // exclusive intra-warp
    float eA = __shfl_up_sync(0xffffffffu, Ai, 1);
    float eU = __shfl_up_sync(0xffffffffu, Ui, 1);
    if (lane == 0) { eA = 1.f; eU = 0.f; }
    // carry = (warp prefix) then (intra-warp exclusive); s0 = 0 -> s_in = carry U
    float s = pU[w] * eA + eU;

    float* st = g_states + (b * 4096 + tid * 16) * 16 + n;
#pragma unroll
    for (int i = 0; i < 16; i++) {
        s = a[i] * s + u[i];
        st[i * 16] = s;
    }
}

// ---------------- K6: out = x + b_out + states @ MT ----------------
// grid: 8192 blocks (one token) x 256 threads
__global__ void k_out(const float* __restrict__ x, const float* __restrict__ bo,
                      float* __restrict__ out) {
    int t = blockIdx.x;
    int tid = threadIdx.x;
    __shared__ float st[16];
    if (tid < 16) st[tid] = g_states[t * 16 + tid];
    __syncthreads();

    float4 v = ((const float4*)(x + t * 1024))[tid];
    float4 b4 = ((const float4*)bo)[tid];
    float r0 = v.x + b4.x, r1 = v.y + b4.y, r2 = v.z + b4.z, r3 = v.w + b4.w;
    int d0 = tid * 4;
#pragma unroll
    for (int n = 0; n < 16; n++) {
        float s = st[n];
        float4 m = *((const float4*)(g_MT + n * 1024 + d0));
        r0 += s * m.x; r1 += s * m.y; r2 += s * m.z; r3 += s * m.w;
    }
    ((float4*)(out + t * 1024))[tid] = make_float4(r0, r1, r2, r3);
}

// ---------------- launch ----------------
extern "C" void kernel_launch(void* const* d_in, const int* in_sizes, int n_in,
                              void* d_out, int out_size) {
    const float* x    = (const float*)d_in[0];
    const float* nw   = (const float*)d_in[1];
    const float* nb   = (const float*)d_in[2];
    const float* Win  = (const float*)d_in[3];
    const float* b_in = (const float*)d_in[4];
    const float* A    = (const float*)d_in[5];
    const float* Bs   = (const float*)d_in[6];
    const float* C    = (const float*)d_in[7];
    const float* Wout = (const float*)d_in[8];
    const float* bo   = (const float*)d_in[9];
    float* out = (float*)d_out;

    k_zero<<<128, 256>>>();
    k_pw  <<<256, 128>>>(Win, A, Bs);
    k_m   <<<1026, 256>>>(Wout, C, A, Bs, b_in);
    k_fold<<<32, 256>>>(nw, nb);
    k_ln  <<<8192, 256>>>(x);
    k_scan<<<32, 256>>>();
    k_out <<<8192, 256>>>(x, bo, out);
}

// round 2
// speedup vs baseline: 4.4105x; 4.4105x over previous
#include <cuda_runtime.h>
#include <math.h>

#define D_MODEL 1024
#define D_STATE 16
#define D_INNER 2048
#define BATCH   2
#define SEQ     4096
#define NTOK    (BATCH*SEQ)

// ---------------- scratch (device globals) ----------------
__device__ __align__(16) float g_Ppart[32 * 32 * 1024]; // [e-chunk][o][d] split-K partials
__device__ __align__(16) float g_Pp[1024 * 32];         // [d][o] P' = nw[d]*P[d][o]
__device__ __align__(16) float g_MT[16 * 1024];         // [n][d] (W_out @ C)^T
__device__ float g_c[32];                               // b_in @ A (0:16), b_in @ B (16:32)
__device__ float g_k1[32];
__device__ float g_k2[32];
__device__ __align__(16) float g_au[BATCH * 32 * SEQ];  // [b][o][s]; o<16: a, o>=16: u
__device__ __align__(16) float g_states[BATCH * 16 * SEQ]; // TRANSPOSED: [b*16+n][s]

// ---------------- K1: split-K partials P^T[o][d] (no atomics) ----------------
// grid 256 (= 8 d-tiles x 32 e-chunks of 64), 128 threads
__global__ void k_pw(const float* __restrict__ Win, const float* __restrict__ A,
                     const float* __restrict__ Bs) {
    __shared__ float sA[64 * 16];
    __shared__ float sB[64 * 16];
    int tid = threadIdx.x;
    int d0 = (blockIdx.x & 7) * 128;
    int chunk = blockIdx.x >> 3;
    int e0 = chunk * 64;
    for (int i = tid; i < 64 * 16; i += 128) {
        sA[i] = A[e0 * 16 + i];
        sB[i] = Bs[e0 * 16 + i];
    }
    __syncthreads();
    float acc[32];
#pragma unroll
    for (int o = 0; o < 32; o++) acc[o] = 0.f;
    int d = d0 + tid;
#pragma unroll 4
    for (int el = 0; el < 64; el++) {
        float w = Win[(e0 + el) * 1024 + d];
#pragma unroll
        for (int n = 0; n < 16; n++) {
            acc[n]      += w * sA[el * 16 + n];
            acc[16 + n] += w * sB[el * 16 + n];
        }
    }
#pragma unroll
    for (int o = 0; o < 32; o++) g_Ppart[(chunk * 32 + o) * 1024 + d] = acc[o];
}

// ---------------- K2: MT[n][d] = W_out @ C ; cA/cB = b_in @ {A|B} ----------------
__global__ void k_m(const float* __restrict__ Wout, const float* __restrict__ C,
                    const float* __restrict__ A, const float* __restrict__ Bs,
                    const float* __restrict__ b_in) {
    int blk = blockIdx.x;
    int tid = threadIdx.x;
    int lane = tid & 31, w = tid >> 5;
    float acc[16];
#pragma unroll
    for (int n = 0; n < 16; n++) acc[n] = 0.f;

    if (blk < 1024) {
        const float* row = Wout + blk * 2048;
        for (int e = tid; e < 2048; e += 256) {
            float wv = row[e];
            const float4* c4 = (const float4*)(C + e * 16);
            float4 c0 = c4[0], c1 = c4[1], c2 = c4[2], c3 = c4[3];
            acc[0] += wv * c0.x; acc[1] += wv * c0.y; acc[2] += wv * c0.z; acc[3] += wv * c0.w;
            acc[4] += wv * c1.x; acc[5] += wv * c1.y; acc[6] += wv * c1.z; acc[7] += wv * c1.w;
            acc[8] += wv * c2.x; acc[9] += wv * c2.y; acc[10]+= wv * c2.z; acc[11]+= wv * c2.w;
            acc[12]+= wv * c3.x; acc[13]+= wv * c3.y; acc[14]+= wv * c3.z; acc[15]+= wv * c3.w;
        }
    } else {
        const float* G = (blk == 1024) ? A : Bs;
        for (int e = tid; e < 2048; e += 256) {
            float bv = b_in[e];
            const float4* g4 = (const float4*)(G + e * 16);
            float4 c0 = g4[0], c1 = g4[1], c2 = g4[2], c3 = g4[3];
            acc[0] += bv * c0.x; acc[1] += bv * c0.y; acc[2] += bv * c0.z; acc[3] += bv * c0.w;
            acc[4] += bv * c1.x; acc[5] += bv * c1.y; acc[6] += bv * c1.z; acc[7] += bv * c1.w;
            acc[8] += bv * c2.x; acc[9] += bv * c2.y; acc[10]+= bv * c2.z; acc[11]+= bv * c2.w;
            acc[12]+= bv * c3.x; acc[13]+= bv * c3.y; acc[14]+= bv * c3.z; acc[15]+= bv * c3.w;
        }
    }
#pragma unroll
    for (int off = 16; off; off >>= 1)
#pragma unroll
        for (int n = 0; n < 16; n++) acc[n] += __shfl_down_sync(0xffffffffu, acc[n], off);

    __shared__ float red[8 * 16];
    if (lane == 0) {
#pragma unroll
        for (int n = 0; n < 16; n++) red[w * 16 + n] = acc[n];
    }
    __syncthreads();
    if (tid < 16) {
        float s = 0.f;
#pragma unroll
        for (int j = 0; j < 8; j++) s += red[j * 16 + tid];
        if (blk < 1024)       g_MT[tid * 1024 + blk] = s;
        else if (blk == 1024) g_c[tid] = s;
        else                  g_c[16 + tid] = s;
    }
}

// ---------------- K3: sum partials, fold LN weights, compute k1/k2 ----------------
// grid 32 (one per o) x 256
__global__ void k_fold(const float* __restrict__ nw, const float* __restrict__ nb) {
    int o = blockIdx.x;
    int tid = threadIdx.x;
    int lane = tid & 31, w = tid >> 5;
    float s1 = 0.f, s2 = 0.f;
    for (int d = tid; d < 1024; d += 256) {
        float p = 0.f;
#pragma unroll
        for (int c = 0; c < 32; c++) p += g_Ppart[(c * 32 + o) * 1024 + d];
        float wn = nw[d];
        s1 += wn * p;
        s2 += nb[d] * p;
        g_Pp[d * 32 + o] = wn * p;
    }
#pragma unroll
    for (int off = 16; off; off >>= 1) {
        s1 += __shfl_down_sync(0xffffffffu, s1, off);
        s2 += __shfl_down_sync(0xffffffffu, s2, off);
    }
    __shared__ float r1[8], r2[8];
    if (lane == 0) { r1[w] = s1; r2[w] = s2; }
    __syncthreads();
    if (tid == 0) {
        float t1 = 0.f, t2 = 0.f;
#pragma unroll
        for (int j = 0; j < 8; j++) { t1 += r1[j]; t2 += r2[j]; }
        g_k1[o] = t1;
        g_k2[o] = t2 + g_c[o];
    }
}

// ---------------- K4: tiled LN + projection GEMM -> a (sigmoid), u ----------------
// grid 256 blocks (32 tokens each) x 128 threads
__global__ void __launch_bounds__(128) k_ln(const float* __restrict__ x) {
    __shared__ float sX[32 * 68];     // padded (68) for conflict-free reads
    __shared__ float sP[64 * 32];
    __shared__ float sMu[32], sRs[32];
    int tid = threadIdx.x;
    int lane = tid & 31, w = tid >> 5;
    int t0 = blockIdx.x * 32;

    // ---- stats: 4 warps x 8 tokens, coalesced float4 reads ----
#pragma unroll
    for (int tk = 0; tk < 8; tk++) {
        int t = w * 8 + tk;
        const float4* xr = (const float4*)(x + (t0 + t) * 1024);
        float s1 = 0.f, s2 = 0.f;
#pragma unroll
        for (int q = 0; q < 8; q++) {
            float4 v = xr[lane + q * 32];
            s1 += v.x + v.y + v.z + v.w;
            s2 += v.x * v.x + v.y * v.y + v.z * v.z + v.w * v.w;
        }
#pragma unroll
        for (int off = 16; off; off >>= 1) {
            s1 += __shfl_down_sync(0xffffffffu, s1, off);
            s2 += __shfl_down_sync(0xffffffffu, s2, off);
        }
        if (lane == 0) {
            float mu = s1 * (1.f / 1024.f);
            float var = s2 * (1.f / 1024.f) - mu * mu;
            sMu[t] = mu;
            sRs[t] = rsqrtf(var + 1e-5f);
        }
    }

    float acc[8];
#pragma unroll
    for (int i = 0; i < 8; i++) acc[i] = 0.f;
    int t = tid >> 2;            // local token 0..31
    int og = (tid & 3) * 8;      // output group base

    for (int c = 0; c < 16; c++) {
        __syncthreads();
        // load x tile: 32 rows x 64 cols (coalesced float4)
#pragma unroll
        for (int it = 0; it < 4; it++) {
            int idx = tid + it * 128;
            int row = idx >> 4, c4 = idx & 15;
            *(float4*)(sX + row * 68 + c4 * 4) =
                *(const float4*)(x + (t0 + row) * 1024 + c * 64 + c4 * 4);
        }
        // load P chunk: 64 rows x 32 cols (coalesced float4)
#pragma unroll
        for (int it = 0; it < 4; it++) {
            int idx = tid + it * 128;
            int row = idx >> 3, c4 = idx & 7;
            *(float4*)(sP + row * 32 + c4 * 4) =
                *(const float4*)(g_Pp + (c * 64 + row) * 32 + c4 * 4);
        }
        __syncthreads();
#pragma unroll
        for (int k = 0; k < 64; k++) {
            float xv = sX[t * 68 + k];
            float4 p0 = *(const float4*)(sP + k * 32 + og);
            float4 p1 = *(const float4*)(sP + k * 32 + og + 4);
            acc[0] += xv * p0.x; acc[1] += xv * p0.y; acc[2] += xv * p0.z; acc[3] += xv * p0.w;
            acc[4] += xv * p1.x; acc[5] += xv * p1.y; acc[6] += xv * p1.z; acc[7] += xv * p1.w;
        }
    }

    float mu = sMu[t], rs = sRs[t];
    int tg = t0 + t;
    int b = tg >> 12, s = tg & 4095;
#pragma unroll
    for (int i = 0; i < 8; i++) {
        int o = og + i;
        float v = rs * acc[i] - mu * rs * g_k1[o] + g_k2[o];
        if (o < 16) v = 1.f / (1.f + __expf(-v));
        g_au[(b * 32 + o) * 4096 + s] = v;
    }
}

// ---------------- K5: 32 parallel diagonal scans, transposed coalesced output ----------------
// grid 32 (bn = b*16+n) x 256, 16 elems/thread
__global__ void k_scan() {
    int bn = blockIdx.x;
    int b = bn >> 4, n = bn & 15;
    const float* ap = g_au + (b * 32 + n) * 4096;
    const float* up = g_au + (b * 32 + 16 + n) * 4096;
    int tid = threadIdx.x;
    int lane = tid & 31, w = tid >> 5;

    float a[16], u[16];
    const float4* a4 = (const float4*)(ap + tid * 16);
    const float4* u4 = (const float4*)(up + tid * 16);
#pragma unroll
    for (int q = 0; q < 4; q++) {
        float4 av = a4[q], uv = u4[q];
        a[q*4+0] = av.x; a[q*4+1] = av.y; a[q*4+2] = av.z; a[q*4+3] = av.w;
        u[q*4+0] = uv.x; u[q*4+1] = uv.y; u[q*4+2] = uv.z; u[q*4+3] = uv.w;
    }
    float Aloc = 1.f, Uloc = 0.f;
#pragma unroll
    for (int i = 0; i < 16; i++) { Uloc = Uloc * a[i] + u[i]; Aloc *= a[i]; }

    float Ai = Aloc, Ui = Uloc;
#pragma unroll
    for (int off = 1; off < 32; off <<= 1) {
        float Ap = __shfl_up_sync(0xffffffffu, Ai, off);
        float Up = __shfl_up_sync(0xffffffffu, Ui, off);
        if (lane >= off) { Ui = Up * Ai + Ui; Ai = Ap * Ai; }
    }
    __shared__ float wA[8], wU[8], pA[8], pU[8];
    if (lane == 31) { wA[w] = Ai; wU[w] = Ui; }
    __syncthreads();
    if (tid == 0) {
        float Ac = 1.f, Uc = 0.f;
#pragma unroll
        for (int j = 0; j < 8; j++) {
            pA[j] = Ac; pU[j] = Uc;
            float na = wA[j], nu = wU[j];
            Uc = Uc * na + nu;
            Ac *= na;
        }
    }
    __syncthreads();
    float eA = __shfl_up_sync(0xffffffffu, Ai, 1);
    float eU = __shfl_up_sync(0xffffffffu, Ui, 1);
    if (lane == 0) { eA = 1.f; eU = 0.f; }
    float s = pU[w] * eA + eU;

    float out[16];
#pragma unroll
    for (int i = 0; i < 16; i++) { s = a[i] * s + u[i]; out[i] = s; }
    float4* dst = (float4*)(g_states + bn * 4096 + tid * 16);
#pragma unroll
    for (int q = 0; q < 4; q++)
        dst[q] = make_float4(out[q*4+0], out[q*4+1], out[q*4+2], out[q*4+3]);
}

// ---------------- K6: out = x + b_out + states @ MT (MT slice in regs) ----------------
// grid 256 blocks (32 tokens each) x 256 threads
__global__ void __launch_bounds__(256) k_out(const float* __restrict__ x,
                                             const float* __restrict__ bo,
                                             float* __restrict__ out) {
    __shared__ float sST[32 * 17];    // [s][n], padded
    int tid = threadIdx.x;
    int t0 = blockIdx.x * 32;
    int b = t0 >> 12, s0 = t0 & 4095;

    // coalesced load of 32 tokens' states from transposed layout
#pragma unroll
    for (int it = 0; it < 2; it++) {
        int idx = tid + it * 256;
        int n = idx >> 5, soff = idx & 31;
        sST[soff * 17 + n] = g_states[(b * 16 + n) * 4096 + s0 + soff];
    }
    // MT slice for this thread's fixed d-range
    float4 m[16];
#pragma unroll
    for (int n = 0; n < 16; n++) m[n] = *(const float4*)(g_MT + n * 1024 + tid * 4);
    float4 bo4 = ((const float4*)bo)[tid];
    __syncthreads();

    for (int t = 0; t < 32; t++) {
        float4 xv = *(const float4*)(x + (t0 + t) * 1024 + tid * 4);
        float r0 = xv.x + bo4.x, r1 = xv.y + bo4.y, r2 = xv.z + bo4.z, r3 = xv.w + bo4.w;
#pragma unroll
        for (int n = 0; n < 16; n++) {
            float sv = sST[t * 17 + n];
            r0 += sv * m[n].x; r1 += sv * m[n].y; r2 += sv * m[n].z; r3 += sv * m[n].w;
        }
        *(float4*)(out + (t0 + t) * 1024 + tid * 4) = make_float4(r0, r1, r2, r3);
    }
}

// ---------------- launch ----------------
extern "C" void kernel_launch(void* const* d_in, const int* in_sizes, int n_in,
                              void* d_out, int out_size) {
    const float* x    = (const float*)d_in[0];
    const float* nw   = (const float*)d_in[1];
    const float* nb   = (const float*)d_in[2];
    const float* Win  = (const float*)d_in[3];
    const float* b_in = (const float*)d_in[4];
    const float* A    = (const float*)d_in[5];
    const float* Bs   = (const float*)d_in[6];
    const float* C    = (const float*)d_in[7];
    const float* Wout = (const float*)d_in[8];
    const float* bo   = (const float*)d_in[9];
    float* out = (float*)d_out;

    k_pw  <<<256, 128>>>(Win, A, Bs);
    k_m   <<<1026, 256>>>(Wout, C, A, Bs, b_in);
    k_fold<<<32, 256>>>(nw, nb);
    k_ln  <<<256, 128>>>(x);
    k_scan<<<32, 256>>>();
    k_out <<<256, 256>>>(x, bo, out);
}

// round 3
// speedup vs baseline: 4.9232x; 1.1162x over previous
#include <cuda_runtime.h>
#include <math.h>

#define D_MODEL 1024
#define D_STATE 16
#define D_INNER 2048
#define BATCH   2
#define SEQ     4096
#define NTOK    (BATCH*SEQ)
#define NCHUNK  16              // split-K chunks for P

// ---------------- scratch ----------------
__device__ __align__(16) float g_Ppart[NCHUNK * 32 * 1024]; // [chunk][o][d]
__device__ __align__(16) float g_Pp[1024 * 32];             // [d][o] P' = nw[d]*P[d][o]
__device__ __align__(16) float g_MT[16 * 1024];             // [n][d]
__device__ float g_c[32];
__device__ float g_k1[32];
__device__ float g_k2[32];
__device__ __align__(16) float g_au[BATCH * 32 * SEQ];      // [b][o][s]
__device__ __align__(16) float g_states[BATCH * 16 * SEQ];  // [b*16+n][s]

// ---------------- K1: merged prologue: split-K P partials  +  MT/c ----------------
// grid = 64 (pw: 4 d-tiles x 16 e-chunks) + 1026 (m) = 1090 blocks, 256 threads
__global__ void __launch_bounds__(256) k_pm(const float* __restrict__ Win,
                                            const float* __restrict__ A,
                                            const float* __restrict__ Bs,
                                            const float* __restrict__ Wout,
                                            const float* __restrict__ C,
                                            const float* __restrict__ b_in) {
    __shared__ float sA[128 * 16];
    __shared__ float sB[128 * 16];
    int blk = blockIdx.x;
    int tid = threadIdx.x;

    if (blk < 64) {
        // ---- pw part: P^T partial over e-chunk ----
        int d0 = (blk & 3) * 256;
        int chunk = blk >> 2;
        int e0 = chunk * 128;
        for (int i = tid; i < 128 * 16; i += 256) {
            sA[i] = A[e0 * 16 + i];
            sB[i] = Bs[e0 * 16 + i];
        }
        __syncthreads();
        float acc[32];
#pragma unroll
        for (int o = 0; o < 32; o++) acc[o] = 0.f;
        int d = d0 + tid;
#pragma unroll 4
        for (int el = 0; el < 128; el++) {
            float w = Win[(e0 + el) * 1024 + d];
#pragma unroll
            for (int n = 0; n < 16; n++) {
                acc[n]      += w * sA[el * 16 + n];
                acc[16 + n] += w * sB[el * 16 + n];
            }
        }
#pragma unroll
        for (int o = 0; o < 32; o++) g_Ppart[(chunk * 32 + o) * 1024 + d] = acc[o];
        return;
    }

    // ---- m part ----
    int mblk = blk - 64;
    int lane = tid & 31, w = tid >> 5;
    float acc[16];
#pragma unroll
    for (int n = 0; n < 16; n++) acc[n] = 0.f;

    if (mblk < 1024) {
        const float* row = Wout + mblk * 2048;
        for (int e = tid; e < 2048; e += 256) {
            float wv = row[e];
            const float4* c4 = (const float4*)(C + e * 16);
            float4 c0 = c4[0], c1 = c4[1], c2 = c4[2], c3 = c4[3];
            acc[0] += wv * c0.x; acc[1] += wv * c0.y; acc[2] += wv * c0.z; acc[3] += wv * c0.w;
            acc[4] += wv * c1.x; acc[5] += wv * c1.y; acc[6] += wv * c1.z; acc[7] += wv * c1.w;
            acc[8] += wv * c2.x; acc[9] += wv * c2.y; acc[10]+= wv * c2.z; acc[11]+= wv * c2.w;
            acc[12]+= wv * c3.x; acc[13]+= wv * c3.y; acc[14]+= wv * c3.z; acc[15]+= wv * c3.w;
        }
    } else {
        const float* G = (mblk == 1024) ? A : Bs;
        for (int e = tid; e < 2048; e += 256) {
            float bv = b_in[e];
            const float4* g4 = (const float4*)(G + e * 16);
            float4 c0 = g4[0], c1 = g4[1], c2 = g4[2], c3 = g4[3];
            acc[0] += bv * c0.x; acc[1] += bv * c0.y; acc[2] += bv * c0.z; acc[3] += bv * c0.w;
            acc[4] += bv * c1.x; acc[5] += bv * c1.y; acc[6] += bv * c1.z; acc[7] += bv * c1.w;
            acc[8] += bv * c2.x; acc[9] += bv * c2.y; acc[10]+= bv * c2.z; acc[11]+= bv * c2.w;
            acc[12]+= bv * c3.x; acc[13]+= bv * c3.y; acc[14]+= bv * c3.z; acc[15]+= bv * c3.w;
        }
    }
#pragma unroll
    for (int off = 16; off; off >>= 1)
#pragma unroll
        for (int n = 0; n < 16; n++) acc[n] += __shfl_down_sync(0xffffffffu, acc[n], off);

    float* red = sA;   // reuse smem
    if (lane == 0) {
#pragma unroll
        for (int n = 0; n < 16; n++) red[w * 16 + n] = acc[n];
    }
    __syncthreads();
    if (tid < 16) {
        float s = 0.f;
#pragma unroll
        for (int j = 0; j < 8; j++) s += red[j * 16 + tid];
        if (mblk < 1024)       g_MT[tid * 1024 + mblk] = s;
        else if (mblk == 1024) g_c[tid] = s;
        else                   g_c[16 + tid] = s;
    }
}

// ---------------- K2: sum partials, fold LN weights, k1/k2 ----------------
__global__ void k_fold(const float* __restrict__ nw, const float* __restrict__ nb) {
    int o = blockIdx.x;
    int tid = threadIdx.x;
    int lane = tid & 31, w = tid >> 5;
    float s1 = 0.f, s2 = 0.f;
    for (int d = tid; d < 1024; d += 256) {
        float p = 0.f;
#pragma unroll
        for (int c = 0; c < NCHUNK; c++) p += g_Ppart[(c * 32 + o) * 1024 + d];
        float wn = nw[d];
        s1 += wn * p;
        s2 += nb[d] * p;
        g_Pp[d * 32 + o] = wn * p;
    }
#pragma unroll
    for (int off = 16; off; off >>= 1) {
        s1 += __shfl_down_sync(0xffffffffu, s1, off);
        s2 += __shfl_down_sync(0xffffffffu, s2, off);
    }
    __shared__ float r1[8], r2[8];
    if (lane == 0) { r1[w] = s1; r2[w] = s2; }
    __syncthreads();
    if (tid == 0) {
        float t1 = 0.f, t2 = 0.f;
#pragma unroll
        for (int j = 0; j < 8; j++) { t1 += r1[j]; t2 += r2[j]; }
        g_k1[o] = t1;
        g_k2[o] = t2 + g_c[o];
    }
}

// ---------------- K3: fused LN + projection, f32x2-packed FMA ----------------
// grid 256 blocks (32 tokens) x 128 threads; thread = (token, 8-output group)
__global__ void __launch_bounds__(128) k_ln(const float* __restrict__ x) {
    __shared__ __align__(16) float sX[32 * 132];   // [t][k] padded
    __shared__ __align__(16) float sP[128 * 32];   // [k][o]
    int tid = threadIdx.x;
    int t0 = blockIdx.x * 32;
    int t = tid >> 2;
    int og = (tid & 3) * 8;

    unsigned long long a0 = 0, a1 = 0, a2 = 0, a3 = 0;
    float s1 = 0.f, s2 = 0.f;

    for (int c = 0; c < 8; c++) {
        __syncthreads();
#pragma unroll
        for (int it = 0; it < 8; it++) {
            int idx = tid + it * 128;
            int row = idx >> 5, col = idx & 31;
            *(float4*)(sX + row * 132 + col * 4) =
                *(const float4*)(x + (t0 + row) * 1024 + c * 128 + col * 4);
        }
#pragma unroll
        for (int it = 0; it < 8; it++) {
            int idx = tid + it * 128;
            int row = idx >> 3, col = idx & 7;
            *(float4*)(sP + row * 32 + col * 4) =
                *(const float4*)(g_Pp + (c * 128 + row) * 32 + col * 4);
        }
        __syncthreads();

        const float* xr = sX + t * 132;
#pragma unroll 32
        for (int k = 0; k < 128; k++) {
            float xv = xr[k];
            unsigned long long xx;
            asm("mov.b64 %0, {%1, %1};" : "=l"(xx) : "f"(xv));
            ulonglong2 pA = *(const ulonglong2*)(sP + k * 32 + og);
            ulonglong2 pB = *(const ulonglong2*)(sP + k * 32 + og + 4);
            asm("fma.rn.f32x2 %0, %1, %2, %0;" : "+l"(a0) : "l"(xx), "l"(pA.x));
            asm("fma.rn.f32x2 %0, %1, %2, %0;" : "+l"(a1) : "l"(xx), "l"(pA.y));
            asm("fma.rn.f32x2 %0, %1, %2, %0;" : "+l"(a2) : "l"(xx), "l"(pB.x));
            asm("fma.rn.f32x2 %0, %1, %2, %0;" : "+l"(a3) : "l"(xx), "l"(pB.y));
            s1 += xv;
            s2 = fmaf(xv, xv, s2);
        }
    }

    float v[8];
    asm("mov.b64 {%0, %1}, %2;" : "=f"(v[0]), "=f"(v[1]) : "l"(a0));
    asm("mov.b64 {%0, %1}, %2;" : "=f"(v[2]), "=f"(v[3]) : "l"(a1));
    asm("mov.b64 {%0, %1}, %2;" : "=f"(v[4]), "=f"(v[5]) : "l"(a2));
    asm("mov.b64 {%0, %1}, %2;" : "=f"(v[6]), "=f"(v[7]) : "l"(a3));

    float mu   = s1 * (1.f / 1024.f);
    float var  = s2 * (1.f / 1024.f) - mu * mu;
    float rs   = rsqrtf(var + 1e-5f);
    int tg = t0 + t;
    int b = tg >> 12, s = tg & 4095;
#pragma unroll
    for (int i = 0; i < 8; i++) {
        int o = og + i;
        float val = rs * v[i] - mu * rs * g_k1[o] + g_k2[o];
        if (o < 16) val = 1.f / (1.f + __expf(-val));
        g_au[(b * 32 + o) * 4096 + s] = val;
    }
}

// ---------------- K4: 32 parallel scans ----------------
__global__ void k_scan() {
    int bn = blockIdx.x;
    int b = bn >> 4, n = bn & 15;
    const float* ap = g_au + (b * 32 + n) * 4096;
    const float* up = g_au + (b * 32 + 16 + n) * 4096;
    int tid = threadIdx.x;
    int lane = tid & 31, w = tid >> 5;

    float a[16], u[16];
    const float4* a4 = (const float4*)(ap + tid * 16);
    const float4* u4 = (const float4*)(up + tid * 16);
#pragma unroll
    for (int q = 0; q < 4; q++) {
        float4 av = a4[q], uv = u4[q];
        a[q*4+0] = av.x; a[q*4+1] = av.y; a[q*4+2] = av.z; a[q*4+3] = av.w;
        u[q*4+0] = uv.x; u[q*4+1] = uv.y; u[q*4+2] = uv.z; u[q*4+3] = uv.w;
    }
    float Aloc = 1.f, Uloc = 0.f;
#pragma unroll
    for (int i = 0; i < 16; i++) { Uloc = Uloc * a[i] + u[i]; Aloc *= a[i]; }

    float Ai = Aloc, Ui = Uloc;
#pragma unroll
    for (int off = 1; off < 32; off <<= 1) {
        float Ap = __shfl_up_sync(0xffffffffu, Ai, off);
        float Up = __shfl_up_sync(0xffffffffu, Ui, off);
        if (lane >= off) { Ui = Up * Ai + Ui; Ai = Ap * Ai; }
    }
    __shared__ float wA[8], wU[8], pU[8];
    if (lane == 31) { wA[w] = Ai; wU[w] = Ui; }
    __syncthreads();
    if (tid == 0) {
        float Ac = 1.f, Uc = 0.f;
#pragma unroll
        for (int j = 0; j < 8; j++) {
            pU[j] = Uc;
            float na = wA[j], nu = wU[j];
            Uc = Uc * na + nu;
            Ac *= na;
        }
    }
    __syncthreads();
    float eA = __shfl_up_sync(0xffffffffu, Ai, 1);
    float eU = __shfl_up_sync(0xffffffffu, Ui, 1);
    if (lane == 0) { eA = 1.f; eU = 0.f; }
    float s = pU[w] * eA + eU;

    float out[16];
#pragma unroll
    for (int i = 0; i < 16; i++) { s = a[i] * s + u[i]; out[i] = s; }
    float4* dst = (float4*)(g_states + bn * 4096 + tid * 16);
#pragma unroll
    for (int q = 0; q < 4; q++)
        dst[q] = make_float4(out[q*4+0], out[q*4+1], out[q*4+2], out[q*4+3]);
}

// ---------------- K5: out = x + b_out + states @ MT ----------------
__global__ void __launch_bounds__(256) k_out(const float* __restrict__ x,
                                             const float* __restrict__ bo,
                                             float* __restrict__ out) {
    __shared__ float sST[32 * 17];
    int tid = threadIdx.x;
    int t0 = blockIdx.x * 32;
    int b = t0 >> 12, s0 = t0 & 4095;

#pragma unroll
    for (int it = 0; it < 2; it++) {
        int idx = tid + it * 256;
        int n = idx >> 5, soff = idx & 31;
        sST[soff * 17 + n] = g_states[(b * 16 + n) * 4096 + s0 + soff];
    }
    float4 m[16];
#pragma unroll
    for (int n = 0; n < 16; n++) m[n] = *(const float4*)(g_MT + n * 1024 + tid * 4);
    float4 bo4 = ((const float4*)bo)[tid];
    __syncthreads();

    for (int t = 0; t < 32; t++) {
        float4 xv = *(const float4*)(x + (t0 + t) * 1024 + tid * 4);
        float r0 = xv.x + bo4.x, r1 = xv.y + bo4.y, r2 = xv.z + bo4.z, r3 = xv.w + bo4.w;
#pragma unroll
        for (int n = 0; n < 16; n++) {
            float sv = sST[t * 17 + n];
            r0 += sv * m[n].x; r1 += sv * m[n].y; r2 += sv * m[n].z; r3 += sv * m[n].w;
        }
        *(float4*)(out + (t0 + t) * 1024 + tid * 4) = make_float4(r0, r1, r2, r3);
    }
}

// ---------------- launch ----------------
extern "C" void kernel_launch(void* const* d_in, const int* in_sizes, int n_in,
                              void* d_out, int out_size) {
    const float* x    = (const float*)d_in[0];
    const float* nw   = (const float*)d_in[1];
    const float* nb   = (const float*)d_in[2];
    const float* Win  = (const float*)d_in[3];
    const float* b_in = (const float*)d_in[4];
    const float* A    = (const float*)d_in[5];
    const float* Bs   = (const float*)d_in[6];
    const float* C    = (const float*)d_in[7];
    const float* Wout = (const float*)d_in[8];
    const float* bo   = (const float*)d_in[9];
    float* out = (float*)d_out;

    k_pm  <<<1090, 256>>>(Win, A, Bs, Wout, C, b_in);
    k_fold<<<32, 256>>>(nw, nb);
    k_ln  <<<256, 128>>>(x);
    k_scan<<<32, 256>>>();
    k_out <<<256, 256>>>(x, bo, out);
}

// round 4
// speedup vs baseline: 5.0278x; 1.0212x over previous
#include <cuda_runtime.h>
#include <math.h>

#define D_MODEL 1024
#define D_STATE 16
#define D_INNER 2048
#define BATCH   2
#define SEQ     4096
#define NTOK    (BATCH*SEQ)
#define NCHUNK  16

// ---------------- scratch ----------------
__device__ __align__(16) float g_Ppart[NCHUNK * 32 * 1024]; // [chunk][o][d]
__device__ __align__(16) float g_MTp[4 * 16 * 1024];        // [quarter][n][d]
__device__ __align__(16) float g_Pp[1024 * 32];             // [d][o]
__device__ __align__(16) float g_MT[16 * 1024];             // [n][d]
__device__ float g_c[32];
__device__ float g_k1[32];
__device__ float g_k2[32];
__device__ __align__(16) float g_au[BATCH * 32 * SEQ];      // [b][o][s]
__device__ __align__(16) float g_states[BATCH * 16 * SEQ];  // [b*16+n][s]

__device__ __forceinline__ unsigned long long dup_f(float v) {
    unsigned long long r;
    asm("mov.b64 %0, {%1, %1};" : "=l"(r) : "f"(v));
    return r;
}

// ---------------- K1: merged prologue ----------------
// blocks 0..63   : P split-K   (4 d-tiles of 256  x 16 e-chunks of 128)
// blocks 64..127 : MT split-K  (16 row-tiles of 64 x 4 e-quarters of 512)
// blocks 128..129: c = b_in @ {A|B}
__global__ void __launch_bounds__(256) k_pm(const float* __restrict__ Win,
                                            const float* __restrict__ A,
                                            const float* __restrict__ Bs,
                                            const float* __restrict__ Wout,
                                            const float* __restrict__ C,
                                            const float* __restrict__ b_in) {
    int blk = blockIdx.x;
    int tid = threadIdx.x;

    if (blk < 64) {
        // ---- P^T partials, f32x2 over d-pairs ----
        __shared__ __align__(16) unsigned long long sAB2[128 * 32]; // {v,v} pairs
        int dt = blk >> 4;              // d-tile (256 cols)
        int chunk = blk & 15;           // e-chunk (128 rows)
        int e0 = chunk * 128;
        for (int i = tid; i < 128 * 16; i += 256) {
            int el = i >> 4, n = i & 15;
            sAB2[el * 32 + n]      = dup_f(A [(e0 + el) * 16 + n]);
            sAB2[el * 32 + 16 + n] = dup_f(Bs[(e0 + el) * 16 + n]);
        }
        __syncthreads();
        int dp = tid >> 1, oh = tid & 1;
        int d = dt * 256 + dp * 2;
        unsigned long long acc[16];
#pragma unroll
        for (int o = 0; o < 16; o++) acc[o] = 0ull;
#pragma unroll 4
        for (int el = 0; el < 128; el++) {
            unsigned long long w01 = *(const unsigned long long*)(Win + (e0 + el) * 1024 + d);
            const unsigned long long* base = sAB2 + el * 32 + oh * 16;
#pragma unroll
            for (int o = 0; o < 16; o++)
                asm("fma.rn.f32x2 %0, %1, %2, %0;" : "+l"(acc[o]) : "l"(w01), "l"(base[o]));
        }
#pragma unroll
        for (int o = 0; o < 16; o++) {
            int oi = oh * 16 + o;
            *(unsigned long long*)(g_Ppart + (chunk * 32 + oi) * 1024 + d) = acc[o];
        }
        return;
    }

    if (blk < 128) {
        // ---- MT partials: Wout loaded once (float4), C chunk in smem ----
        __shared__ __align__(16) float sC[128 * 16]; // 8KB
        int mb = blk - 64;
        int tile = mb >> 2;             // 16 row-tiles of 64
        int q = mb & 3;                 // e-quarter of 512
        int row = tile * 64 + (tid >> 2);
        int nq = tid & 3;
        unsigned long long acc0 = 0ull, acc1 = 0ull;
        for (int c = 0; c < 4; c++) {
            int e0 = q * 512 + c * 128;
            __syncthreads();
            for (int i = tid; i < 512; i += 256)
                ((float4*)sC)[i] = ((const float4*)(C + e0 * 16))[i];
            __syncthreads();
            const float* wrow = Wout + row * 2048 + e0;
#pragma unroll 8
            for (int g = 0; g < 32; g++) {
                float4 w4 = *(const float4*)(wrow + g * 4);
#pragma unroll
                for (int j = 0; j < 4; j++) {
                    float wv = (j == 0) ? w4.x : (j == 1) ? w4.y : (j == 2) ? w4.z : w4.w;
                    unsigned long long wd = dup_f(wv);
                    ulonglong2 cp = *(const ulonglong2*)(sC + (g * 4 + j) * 16 + nq * 4);
                    asm("fma.rn.f32x2 %0, %1, %2, %0;" : "+l"(acc0) : "l"(wd), "l"(cp.x));
                    asm("fma.rn.f32x2 %0, %1, %2, %0;" : "+l"(acc1) : "l"(wd), "l"(cp.y));
                }
            }
        }
        float a[4];
        asm("mov.b64 {%0, %1}, %2;" : "=f"(a[0]), "=f"(a[1]) : "l"(acc0));
        asm("mov.b64 {%0, %1}, %2;" : "=f"(a[2]), "=f"(a[3]) : "l"(acc1));
#pragma unroll
        for (int i = 0; i < 4; i++) {
            int n = nq * 4 + i;
            g_MTp[(q * 16 + n) * 1024 + row] = a[i];
        }
        return;
    }

    // ---- bias: c = b_in @ {A|B} ----
    {
        __shared__ float red[8 * 16];
        int lane = tid & 31, w = tid >> 5;
        const float* G = (blk == 128) ? A : Bs;
        float acc[16];
#pragma unroll
        for (int n = 0; n < 16; n++) acc[n] = 0.f;
        for (int e = tid; e < 2048; e += 256) {
            float bv = b_in[e];
            const float4* g4 = (const float4*)(G + e * 16);
            float4 c0 = g4[0], c1 = g4[1], c2 = g4[2], c3 = g4[3];
            acc[0] += bv * c0.x; acc[1] += bv * c0.y; acc[2] += bv * c0.z; acc[3] += bv * c0.w;
            acc[4] += bv * c1.x; acc[5] += bv * c1.y; acc[6] += bv * c1.z; acc[7] += bv * c1.w;
            acc[8] += bv * c2.x; acc[9] += bv * c2.y; acc[10]+= bv * c2.z; acc[11]+= bv * c2.w;
            acc[12]+= bv * c3.x; acc[13]+= bv * c3.y; acc[14]+= bv * c3.z; acc[15]+= bv * c3.w;
        }
#pragma unroll
        for (int off = 16; off; off >>= 1)
#pragma unroll
            for (int n = 0; n < 16; n++) acc[n] += __shfl_down_sync(0xffffffffu, acc[n], off);
        if (lane == 0) {
#pragma unroll
            for (int n = 0; n < 16; n++) red[w * 16 + n] = acc[n];
        }
        __syncthreads();
        if (tid < 16) {
            float s = 0.f;
#pragma unroll
            for (int j = 0; j < 8; j++) s += red[j * 16 + tid];
            if (blk == 128) g_c[tid] = s; else g_c[16 + tid] = s;
        }
    }
}

// ---------------- K2: fold (blocks 0..31: P; blocks 32..47: MT sum) ----------------
__global__ void k_fold(const float* __restrict__ nw, const float* __restrict__ nb) {
    int blk = blockIdx.x;
    int tid = threadIdx.x;
    if (blk >= 32) {
        int tile = blk - 32;
        for (int i = tid; i < 1024; i += 256) {
            int d = tile * 64 + (i >> 4), n = i & 15;
            float s = 0.f;
#pragma unroll
            for (int q = 0; q < 4; q++) s += g_MTp[(q * 16 + n) * 1024 + d];
            g_MT[n * 1024 + d] = s;
        }
        return;
    }
    int o = blk;
    int lane = tid & 31, w = tid >> 5;
    float s1 = 0.f, s2 = 0.f;
    for (int d = tid; d < 1024; d += 256) {
        float p = 0.f;
#pragma unroll
        for (int c = 0; c < NCHUNK; c++) p += g_Ppart[(c * 32 + o) * 1024 + d];
        float wn = nw[d];
        s1 += wn * p;
        s2 += nb[d] * p;
        g_Pp[d * 32 + o] = wn * p;
    }
#pragma unroll
    for (int off = 16; off; off >>= 1) {
        s1 += __shfl_down_sync(0xffffffffu, s1, off);
        s2 += __shfl_down_sync(0xffffffffu, s2, off);
    }
    __shared__ float r1[8], r2[8];
    if (lane == 0) { r1[w] = s1; r2[w] = s2; }
    __syncthreads();
    if (tid == 0) {
        float t1 = 0.f, t2 = 0.f;
#pragma unroll
        for (int j = 0; j < 8; j++) { t1 += r1[j]; t2 += r2[j]; }
        g_k1[o] = t1;
        g_k2[o] = t2 + g_c[o];
    }
}

// ---------------- K3: fused LN + projection (f32x2) ----------------
__global__ void __launch_bounds__(128) k_ln(const float* __restrict__ x) {
    __shared__ __align__(16) float sX[32 * 132];
    __shared__ __align__(16) float sP[128 * 32];
    int tid = threadIdx.x;
    int t0 = blockIdx.x * 32;
    int t = tid >> 2;
    int og = (tid & 3) * 8;

    unsigned long long a0 = 0, a1 = 0, a2 = 0, a3 = 0;
    float s1 = 0.f, s2 = 0.f;

    for (int c = 0; c < 8; c++) {
        __syncthreads();
#pragma unroll
        for (int it = 0; it < 8; it++) {
            int idx = tid + it * 128;
            int row = idx >> 5, col = idx & 31;
            *(float4*)(sX + row * 132 + col * 4) =
                *(const float4*)(x + (t0 + row) * 1024 + c * 128 + col * 4);
        }
#pragma unroll
        for (int it = 0; it < 8; it++) {
            int idx = tid + it * 128;
            int row = idx >> 3, col = idx & 7;
            *(float4*)(sP + row * 32 + col * 4) =
                *(const float4*)(g_Pp + (c * 128 + row) * 32 + col * 4);
        }
        __syncthreads();

        const float* xr = sX + t * 132;
#pragma unroll 32
        for (int k = 0; k < 128; k++) {
            float xv = xr[k];
            unsigned long long xx = dup_f(xv);
            ulonglong2 pA = *(const ulonglong2*)(sP + k * 32 + og);
            ulonglong2 pB = *(const ulonglong2*)(sP + k * 32 + og + 4);
            asm("fma.rn.f32x2 %0, %1, %2, %0;" : "+l"(a0) : "l"(xx), "l"(pA.x));
            asm("fma.rn.f32x2 %0, %1, %2, %0;" : "+l"(a1) : "l"(xx), "l"(pA.y));
            asm("fma.rn.f32x2 %0, %1, %2, %0;" : "+l"(a2) : "l"(xx), "l"(pB.x));
            asm("fma.rn.f32x2 %0, %1, %2, %0;" : "+l"(a3) : "l"(xx), "l"(pB.y));
            s1 += xv;
            s2 = fmaf(xv, xv, s2);
        }
    }

    float v[8];
    asm("mov.b64 {%0, %1}, %2;" : "=f"(v[0]), "=f"(v[1]) : "l"(a0));
    asm("mov.b64 {%0, %1}, %2;" : "=f"(v[2]), "=f"(v[3]) : "l"(a1));
    asm("mov.b64 {%0, %1}, %2;" : "=f"(v[4]), "=f"(v[5]) : "l"(a2));
    asm("mov.b64 {%0, %1}, %2;" : "=f"(v[6]), "=f"(v[7]) : "l"(a3));

    float mu   = s1 * (1.f / 1024.f);
    float var  = s2 * (1.f / 1024.f) - mu * mu;
    float rs   = rsqrtf(var + 1e-5f);
    int tg = t0 + t;
    int b = tg >> 12, s = tg & 4095;
#pragma unroll
    for (int i = 0; i < 8; i++) {
        int o = og + i;
        float val = rs * v[i] - mu * rs * g_k1[o] + g_k2[o];
        if (o < 16) val = 1.f / (1.f + __expf(-val));
        g_au[(b * 32 + o) * 4096 + s] = val;
    }
}

// ---------------- K4: 32 parallel scans, 512 threads ----------------
__global__ void __launch_bounds__(512) k_scan() {
    int bn = blockIdx.x;
    int b = bn >> 4, n = bn & 15;
    const float* ap = g_au + (b * 32 + n) * 4096;
    const float* up = g_au + (b * 32 + 16 + n) * 4096;
    int tid = threadIdx.x;
    int lane = tid & 31, w = tid >> 5;

    float a[8], u[8];
    const float4* a4 = (const float4*)(ap + tid * 8);
    const float4* u4 = (const float4*)(up + tid * 8);
#pragma unroll
    for (int q = 0; q < 2; q++) {
        float4 av = a4[q], uv = u4[q];
        a[q*4+0] = av.x; a[q*4+1] = av.y; a[q*4+2] = av.z; a[q*4+3] = av.w;
        u[q*4+0] = uv.x; u[q*4+1] = uv.y; u[q*4+2] = uv.z; u[q*4+3] = uv.w;
    }
    float Aloc = 1.f, Uloc = 0.f;
#pragma unroll
    for (int i = 0; i < 8; i++) { Uloc = Uloc * a[i] + u[i]; Aloc *= a[i]; }

    float Ai = Aloc, Ui = Uloc;
#pragma unroll
    for (int off = 1; off < 32; off <<= 1) {
        float Ap = __shfl_up_sync(0xffffffffu, Ai, off);
        float Up = __shfl_up_sync(0xffffffffu, Ui, off);
        if (lane >= off) { Ui = Up * Ai + Ui; Ai = Ap * Ai; }
    }
    __shared__ float wA[16], wU[16], pU[16];
    if (lane == 31) { wA[w] = Ai; wU[w] = Ui; }
    __syncthreads();
    if (tid == 0) {
        float Uc = 0.f;
#pragma unroll
        for (int j = 0; j < 16; j++) {
            pU[j] = Uc;
            Uc = Uc * wA[j] + wU[j];
        }
    }
    __syncthreads();
    float eA = __shfl_up_sync(0xffffffffu, Ai, 1);
    float eU = __shfl_up_sync(0xffffffffu, Ui, 1);
    if (lane == 0) { eA = 1.f; eU = 0.f; }
    float s = pU[w] * eA + eU;

    float out[8];
#pragma unroll
    for (int i = 0; i < 8; i++) { s = a[i] * s + u[i]; out[i] = s; }
    float4* dst = (float4*)(g_states + bn * 4096 + tid * 8);
#pragma unroll
    for (int q = 0; q < 2; q++)
        dst[q] = make_float4(out[q*4+0], out[q*4+1], out[q*4+2], out[q*4+3]);
}

// ---------------- K5: out = x + b_out + states @ MT ----------------
__global__ void __launch_bounds__(256) k_out(const float* __restrict__ x,
                                             const float* __restrict__ bo,
                                             float* __restrict__ out) {
    __shared__ float sST[32 * 17];
    int tid = threadIdx.x;
    int t0 = blockIdx.x * 32;
    int b = t0 >> 12, s0 = t0 & 4095;

#pragma unroll
    for (int it = 0; it < 2; it++) {
        int idx = tid + it * 256;
        int n = idx >> 5, soff = idx & 31;
        sST[soff * 17 + n] = g_states[(b * 16 + n) * 4096 + s0 + soff];
    }
    float4 m[16];
#pragma unroll
    for (int n = 0; n < 16; n++) m[n] = *(const float4*)(g_MT + n * 1024 + tid * 4);
    float4 bo4 = ((const float4*)bo)[tid];
    __syncthreads();

    for (int t = 0; t < 32; t++) {
        float4 xv = *(const float4*)(x + (t0 + t) * 1024 + tid * 4);
        float r0 = xv.x + bo4.x, r1 = xv.y + bo4.y, r2 = xv.z + bo4.z, r3 = xv.w + bo4.w;
#pragma unroll
        for (int n = 0; n < 16; n++) {
            float sv = sST[t * 17 + n];
            r0 += sv * m[n].x; r1 += sv * m[n].y; r2 += sv * m[n].z; r3 += sv * m[n].w;
        }
        *(float4*)(out + (t0 + t) * 1024 + tid * 4) = make_float4(r0, r1, r2, r3);
    }
}

// ---------------- launch ----------------
extern "C" void kernel_launch(void* const* d_in, const int* in_sizes, int n_in,
                              void* d_out, int out_size) {
    const float* x    = (const float*)d_in[0];
    const float* nw   = (const float*)d_in[1];
    const float* nb   = (const float*)d_in[2];
    const float* Win  = (const float*)d_in[3];
    const float* b_in = (const float*)d_in[4];
    const float* A    = (const float*)d_in[5];
    const float* Bs   = (const float*)d_in[6];
    const float* C    = (const float*)d_in[7];
    const float* Wout = (const float*)d_in[8];
    const float* bo   = (const float*)d_in[9];
    float* out = (float*)d_out;

    k_pm  <<<130, 256>>>(Win, A, Bs, Wout, C, b_in);
    k_fold<<<48, 256>>>(nw, nb);
    k_ln  <<<256, 128>>>(x);
    k_scan<<<32, 512>>>();
    k_out <<<256, 256>>>(x, bo, out);
}

// round 6
// speedup vs baseline: 5.3045x; 1.0550x over previous
#include <cuda_runtime.h>
#include <math.h>

#define D_MODEL 1024
#define D_STATE 16
#define D_INNER 2048
#define BATCH   2
#define SEQ     4096
#define NTOK    (BATCH*SEQ)
#define NCHUNK  16

// ---------------- scratch ----------------
__device__ __align__(16) float g_Ppart[NCHUNK * 32 * 1024]; // [chunk][o][d]
__device__ __align__(16) float g_MTp[4 * 16 * 1024];        // [quarter][n][d]
__device__ __align__(16) float g_Pp[1024 * 32];             // [d][o]
__device__ __align__(16) float g_MT[16 * 1024];             // [n][d]
__device__ float g_c[32];
__device__ float g_k1[32];
__device__ float g_k2[32];
__device__ __align__(16) float g_au[BATCH * 32 * SEQ];      // [b][o][s]
__device__ __align__(16) float g_states[BATCH * 16 * SEQ];  // [b*16+n][s]

__device__ __forceinline__ unsigned long long dup_f(float v) {
    unsigned long long r;
    asm("mov.b64 %0, {%1, %1};" : "=l"(r) : "f"(v));
    return r;
}
__device__ __forceinline__ void cp16(unsigned int dst, const void* src) {
    asm volatile("cp.async.ca.shared.global [%0], [%1], 16;" :: "r"(dst), "l"(src));
}

// ---------------- K1: merged prologue ----------------
__global__ void __launch_bounds__(256) k_pm(const float* __restrict__ Win,
                                            const float* __restrict__ A,
                                            const float* __restrict__ Bs,
                                            const float* __restrict__ Wout,
                                            const float* __restrict__ C,
                                            const float* __restrict__ b_in) {
    int blk = blockIdx.x;
    int tid = threadIdx.x;

    if (blk < 64) {
        __shared__ __align__(16) unsigned long long sAB2[128 * 32];
        int dt = blk >> 4;
        int chunk = blk & 15;
        int e0 = chunk * 128;
        for (int i = tid; i < 128 * 16; i += 256) {
            int el = i >> 4, n = i & 15;
            sAB2[el * 32 + n]      = dup_f(A [(e0 + el) * 16 + n]);
            sAB2[el * 32 + 16 + n] = dup_f(Bs[(e0 + el) * 16 + n]);
        }
        __syncthreads();
        int dp = tid >> 1, oh = tid & 1;
        int d = dt * 256 + dp * 2;
        unsigned long long acc[16];
#pragma unroll
        for (int o = 0; o < 16; o++) acc[o] = 0ull;
#pragma unroll 4
        for (int el = 0; el < 128; el++) {
            unsigned long long w01 = *(const unsigned long long*)(Win + (e0 + el) * 1024 + d);
            const unsigned long long* base = sAB2 + el * 32 + oh * 16;
#pragma unroll
            for (int o = 0; o < 16; o++)
                asm("fma.rn.f32x2 %0, %1, %2, %0;" : "+l"(acc[o]) : "l"(w01), "l"(base[o]));
        }
#pragma unroll
        for (int o = 0; o < 16; o++) {
            int oi = oh * 16 + o;
            *(unsigned long long*)(g_Ppart + (chunk * 32 + oi) * 1024 + d) = acc[o];
        }
        return;
    }

    if (blk < 128) {
        __shared__ __align__(16) float sC[128 * 16];
        int mb = blk - 64;
        int tile = mb >> 2;
        int q = mb & 3;
        int row = tile * 64 + (tid >> 2);
        int nq = tid & 3;
        unsigned long long acc0 = 0ull, acc1 = 0ull;
        for (int c = 0; c < 4; c++) {
            int e0 = q * 512 + c * 128;
            __syncthreads();
            for (int i = tid; i < 512; i += 256)
                ((float4*)sC)[i] = ((const float4*)(C + e0 * 16))[i];
            __syncthreads();
            const float* wrow = Wout + row * 2048 + e0;
#pragma unroll 8
            for (int g = 0; g < 32; g++) {
                float4 w4 = *(const float4*)(wrow + g * 4);
#pragma unroll
                for (int j = 0; j < 4; j++) {
                    float wv = (j == 0) ? w4.x : (j == 1) ? w4.y : (j == 2) ? w4.z : w4.w;
                    unsigned long long wd = dup_f(wv);
                    ulonglong2 cp = *(const ulonglong2*)(sC + (g * 4 + j) * 16 + nq * 4);
                    asm("fma.rn.f32x2 %0, %1, %2, %0;" : "+l"(acc0) : "l"(wd), "l"(cp.x));
                    asm("fma.rn.f32x2 %0, %1, %2, %0;" : "+l"(acc1) : "l"(wd), "l"(cp.y));
                }
            }
        }
        float a[4];
        asm("mov.b64 {%0, %1}, %2;" : "=f"(a[0]), "=f"(a[1]) : "l"(acc0));
        asm("mov.b64 {%0, %1}, %2;" : "=f"(a[2]), "=f"(a[3]) : "l"(acc1));
#pragma unroll
        for (int i = 0; i < 4; i++) {
            int n = nq * 4 + i;
            g_MTp[(q * 16 + n) * 1024 + row] = a[i];
        }
        return;
    }

    {
        __shared__ float red[8 * 16];
        int lane = tid & 31, w = tid >> 5;
        const float* G = (blk == 128) ? A : Bs;
        float acc[16];
#pragma unroll
        for (int n = 0; n < 16; n++) acc[n] = 0.f;
        for (int e = tid; e < 2048; e += 256) {
            float bv = b_in[e];
            const float4* g4 = (const float4*)(G + e * 16);
            float4 c0 = g4[0], c1 = g4[1], c2 = g4[2], c3 = g4[3];
            acc[0] += bv * c0.x; acc[1] += bv * c0.y; acc[2] += bv * c0.z; acc[3] += bv * c0.w;
            acc[4] += bv * c1.x; acc[5] += bv * c1.y; acc[6] += bv * c1.z; acc[7] += bv * c1.w;
            acc[8] += bv * c2.x; acc[9] += bv * c2.y; acc[10]+= bv * c2.z; acc[11]+= bv * c2.w;
            acc[12]+= bv * c3.x; acc[13]+= bv * c3.y; acc[14]+= bv * c3.z; acc[15]+= bv * c3.w;
        }
#pragma unroll
        for (int off = 16; off; off >>= 1)
#pragma unroll
            for (int n = 0; n < 16; n++) acc[n] += __shfl_down_sync(0xffffffffu, acc[n], off);
        if (lane == 0) {
#pragma unroll
            for (int n = 0; n < 16; n++) red[w * 16 + n] = acc[n];
        }
        __syncthreads();
        if (tid < 16) {
            float s = 0.f;
#pragma unroll
            for (int j = 0; j < 8; j++) s += red[j * 16 + tid];
            if (blk == 128) g_c[tid] = s; else g_c[16 + tid] = s;
        }
    }
}

// ---------------- K2: fold ----------------
__global__ void k_fold(const float* __restrict__ nw, const float* __restrict__ nb) {
    int blk = blockIdx.x;
    int tid = threadIdx.x;
    if (blk >= 32) {
        int tile = blk - 32;
        for (int i = tid; i < 1024; i += 256) {
            int d = tile * 64 + (i >> 4), n = i & 15;
            float s = 0.f;
#pragma unroll
            for (int q = 0; q < 4; q++) s += g_MTp[(q * 16 + n) * 1024 + d];
            g_MT[n * 1024 + d] = s;
        }
        return;
    }
    int o = blk;
    int lane = tid & 31, w = tid >> 5;
    float s1 = 0.f, s2 = 0.f;
    for (int d = tid; d < 1024; d += 256) {
        float p = 0.f;
#pragma unroll
        for (int c = 0; c < NCHUNK; c++) p += g_Ppart[(c * 32 + o) * 1024 + d];
        float wn = nw[d];
        s1 += wn * p;
        s2 += nb[d] * p;
        g_Pp[d * 32 + o] = wn * p;
    }
#pragma unroll
    for (int off = 16; off; off >>= 1) {
        s1 += __shfl_down_sync(0xffffffffu, s1, off);
        s2 += __shfl_down_sync(0xffffffffu, s2, off);
    }
    __shared__ float r1[8], r2[8];
    if (lane == 0) { r1[w] = s1; r2[w] = s2; }
    __syncthreads();
    if (tid == 0) {
        float t1 = 0.f, t2 = 0.f;
#pragma unroll
        for (int j = 0; j < 8; j++) { t1 += r1[j]; t2 += r2[j]; }
        g_k1[o] = t1;
        g_k2[o] = t2 + g_c[o];
    }
}

// ---------------- K3: fused LN+projection, cp.async double-buffered, 64-chunks ----------------
// grid 256 blocks (32 tokens) x 256 threads; thread = (token t = tid>>3, 4 outputs oq = tid&7)
#define XSTRIDE (32 * 68)   // per-buffer floats
#define PSTRIDE (64 * 32)
__global__ void __launch_bounds__(256) k_ln(const float* __restrict__ x) {
    __shared__ __align__(16) float sX[2 * XSTRIDE];   // 17.4KB
    __shared__ __align__(16) float sP[2 * PSTRIDE];   // 16.4KB
    int tid = threadIdx.x;
    int t0 = blockIdx.x * 32;
    int t = tid >> 3;
    int oq = tid & 7;

    unsigned int sxb = (unsigned int)__cvta_generic_to_shared(sX);
    unsigned int spb = (unsigned int)__cvta_generic_to_shared(sP);

    auto load_chunk = [&](int c, int buf) {
#pragma unroll
        for (int it = 0; it < 2; it++) {
            int idx = tid + it * 256;
            int rx = idx >> 4, cx = idx & 15;   // x: 32 rows x 16 float4
            cp16(sxb + (buf * XSTRIDE + rx * 68 + cx * 4) * 4,
                 x + (t0 + rx) * 1024 + c * 64 + cx * 4);
            int rp = idx >> 3, cpn = idx & 7;   // P: 64 rows x 8 float4
            cp16(spb + (buf * PSTRIDE + rp * 32 + cpn * 4) * 4,
                 g_Pp + (c * 64 + rp) * 32 + cpn * 4);
        }
        asm volatile("cp.async.commit_group;");
    };

    unsigned long long a0 = 0, a1 = 0;
    float s1 = 0.f, s2 = 0.f;

    load_chunk(0, 0);
    for (int c = 0; c < 16; c++) {
        int buf = c & 1;
        if (c < 15) {
            load_chunk(c + 1, buf ^ 1);
            asm volatile("cp.async.wait_group 1;");
        } else {
            asm volatile("cp.async.wait_group 0;");
        }
        __syncthreads();

        const float* xr = sX + buf * XSTRIDE + t * 68;
        const float* Pb = sP + buf * PSTRIDE;
#pragma unroll 16
        for (int k = 0; k < 64; k++) {
            float xv = xr[k];
            unsigned long long xx = dup_f(xv);
            ulonglong2 p = *(const ulonglong2*)(Pb + k * 32 + oq * 4);
            asm("fma.rn.f32x2 %0, %1, %2, %0;" : "+l"(a0) : "l"(xx), "l"(p.x));
            asm("fma.rn.f32x2 %0, %1, %2, %0;" : "+l"(a1) : "l"(xx), "l"(p.y));
            s1 += xv;
            s2 = fmaf(xv, xv, s2);
        }
        __syncthreads();
    }

    float v[4];
    asm("mov.b64 {%0, %1}, %2;" : "=f"(v[0]), "=f"(v[1]) : "l"(a0));
    asm("mov.b64 {%0, %1}, %2;" : "=f"(v[2]), "=f"(v[3]) : "l"(a1));

    float mu   = s1 * (1.f / 1024.f);
    float var  = s2 * (1.f / 1024.f) - mu * mu;
    float rs   = rsqrtf(var + 1e-5f);
    int tg = t0 + t;
    int b = tg >> 12, s = tg & 4095;
#pragma unroll
    for (int i = 0; i < 4; i++) {
        int o = oq * 4 + i;
        float val = rs * v[i] - mu * rs * g_k1[o] + g_k2[o];
        if (o < 16) val = 1.f / (1.f + __expf(-val));
        g_au[(b * 32 + o) * 4096 + s] = val;
    }
}

// ---------------- K4: 32 parallel scans ----------------
__global__ void __launch_bounds__(512) k_scan() {
    int bn = blockIdx.x;
    int b = bn >> 4, n = bn & 15;
    const float* ap = g_au + (b * 32 + n) * 4096;
    const float* up = g_au + (b * 32 + 16 + n) * 4096;
    int tid = threadIdx.x;
    int lane = tid & 31, w = tid >> 5;

    float a[8], u[8];
    const float4* a4 = (const float4*)(ap + tid * 8);
    const float4* u4 = (const float4*)(up + tid * 8);
#pragma unroll
    for (int q = 0; q < 2; q++) {
        float4 av = a4[q], uv = u4[q];
        a[q*4+0] = av.x; a[q*4+1] = av.y; a[q*4+2] = av.z; a[q*4+3] = av.w;
        u[q*4+0] = uv.x; u[q*4+1] = uv.y; u[q*4+2] = uv.z; u[q*4+3] = uv.w;
    }
    float Aloc = 1.f, Uloc = 0.f;
#pragma unroll
    for (int i = 0; i < 8; i++) { Uloc = Uloc * a[i] + u[i]; Aloc *= a[i]; }

    float Ai = Aloc, Ui = Uloc;
#pragma unroll
    for (int off = 1; off < 32; off <<= 1) {
        float Ap = __shfl_up_sync(0xffffffffu, Ai, off);
        float Up = __shfl_up_sync(0xffffffffu, Ui, off);
        if (lane >= off) { Ui = Up * Ai + Ui; Ai = Ap * Ai; }
    }
    __shared__ float wA[16], wU[16], pU[16];
    if (lane == 31) { wA[w] = Ai; wU[w] = Ui; }
    __syncthreads();
    if (tid == 0) {
        float Uc = 0.f;
#pragma unroll
        for (int j = 0; j < 16; j++) {
            pU[j] = Uc;
            Uc = Uc * wA[j] + wU[j];
        }
    }
    __syncthreads();
    float eA = __shfl_up_sync(0xffffffffu, Ai, 1);
    float eU = __shfl_up_sync(0xffffffffu, Ui, 1);
    if (lane == 0) { eA = 1.f; eU = 0.f; }
    float s = pU[w] * eA + eU;

    float out[8];
#pragma unroll
    for (int i = 0; i < 8; i++) { s = a[i] * s + u[i]; out[i] = s; }
    float4* dst = (float4*)(g_states + bn * 4096 + tid * 8);
#pragma unroll
    for (int q = 0; q < 2; q++)
        dst[q] = make_float4(out[q*4+0], out[q*4+1], out[q*4+2], out[q*4+3]);
}

// ---------------- K5: out = x + b_out + states @ MT  (f32x2) ----------------
__global__ void __launch_bounds__(256) k_out(const float* __restrict__ x,
                                             const float* __restrict__ bo,
                                             float* __restrict__ out) {
    __shared__ float sST[32 * 17];
    int tid = threadIdx.x;
    int t0 = blockIdx.x * 32;
    int b = t0 >> 12, s0 = t0 & 4095;

#pragma unroll
    for (int it = 0; it < 2; it++) {
        int idx = tid + it * 256;
        int n = idx >> 5, soff = idx & 31;
        sST[soff * 17 + n] = g_states[(b * 16 + n) * 4096 + s0 + soff];
    }
    unsigned long long m01[16], m23[16];
#pragma unroll
    for (int n = 0; n < 16; n++) {
        ulonglong2 mm = *(const ulonglong2*)(g_MT + n * 1024 + tid * 4);
        m01[n] = mm.x; m23[n] = mm.y;
    }
    ulonglong2 bov = *(const ulonglong2*)((const float*)bo + tid * 4);
    __syncthreads();

    for (int t = 0; t < 32; t++) {
        ulonglong2 xv = *(const ulonglong2*)(x + (t0 + t) * 1024 + tid * 4);
        unsigned long long r01, r23;
        asm("add.rn.f32x2 %0, %1, %2;" : "=l"(r01) : "l"(xv.x), "l"(bov.x));
        asm("add.rn.f32x2 %0, %1, %2;" : "=l"(r23) : "l"(xv.y), "l"(bov.y));
#pragma unroll
        for (int n = 0; n < 16; n++) {
            unsigned long long sv = dup_f(sST[t * 17 + n]);
            asm("fma.rn.f32x2 %0, %1, %2, %0;" : "+l"(r01) : "l"(sv), "l"(m01[n]));
            asm("fma.rn.f32x2 %0, %1, %2, %0;" : "+l"(r23) : "l"(sv), "l"(m23[n]));
        }
        ulonglong2 res; res.x = r01; res.y = r23;
        *(ulonglong2*)(out + (t0 + t) * 1024 + tid * 4) = res;
    }
}

// ---------------- launch ----------------
extern "C" void kernel_launch(void* const* d_in, const int* in_sizes, int n_in,
                              void* d_out, int out_size) {
    const float* x    = (const float*)d_in[0];
    const float* nw   = (const float*)d_in[1];
    const float* nb   = (const float*)d_in[2];
    const float* Win  = (const float*)d_in[3];
    const float* b_in = (const float*)d_in[4];
    const float* A    = (const float*)d_in[5];
    const float* Bs   = (const float*)d_in[6];
    const float* C    = (const float*)d_in[7];
    const float* Wout = (const float*)d_in[8];
    const float* bo   = (const float*)d_in[9];
    float* out = (float*)d_out;

    k_pm  <<<130, 256>>>(Win, A, Bs, Wout, C, b_in);
    k_fold<<<48, 256>>>(nw, nb);
    k_ln  <<<256, 256>>>(x);
    k_scan<<<32, 512>>>();
    k_out <<<256, 256>>>(x, bo, out);
}